// round 3
// baseline (speedup 1.0000x reference)
#include <cuda_runtime.h>
#include <math.h>

#define BATCH 512
#define NEG   (-1e9f)

// ---------------- scratch ----------------
__device__ float g_feat[BATCH * 128];
__device__ float g_exh[3 * 128];
__device__ int   g_ops[BATCH * 8 * 3];

// =====================================================================
// exh = emb @ Wxh  (3 x 128): one small block, runs first (independent).
// =====================================================================
__global__ void k_exh(const float* __restrict__ emb, const float* __restrict__ Wxh)
{
    __shared__ float semb[384];
    int tid = threadIdx.x;                 // 384 threads
    semb[tid] = emb[tid];
    __syncthreads();
    int o = tid >> 7, j = tid & 127;
    const float* e = semb + o * 128;
    float acc = 0.f;
    #pragma unroll 8
    for (int d = 0; d < 128; d++) acc += e[d] * Wxh[d * 128 + j];
    g_exh[tid] = acc;
}

// =====================================================================
// Fused conv1+conv2+conv3 (+BN+ReLU+pool each) per image.
// 288 threads/block, 80KB dynamic smem.
// =====================================================================
__global__ void __launch_bounds__(288, 2)
k_conv_all(const float* __restrict__ x,
           const float* __restrict__ w1, const float* __restrict__ cb1,
           const float* __restrict__ g1, const float* __restrict__ bb1,
           const float* __restrict__ m1, const float* __restrict__ v1,
           const float* __restrict__ w2, const float* __restrict__ cb2,
           const float* __restrict__ g2, const float* __restrict__ bb2,
           const float* __restrict__ m2, const float* __restrict__ v2,
           const float* __restrict__ w3, const float* __restrict__ cb3,
           const float* __restrict__ g3, const float* __restrict__ bb3,
           const float* __restrict__ m3, const float* __restrict__ v3)
{
    extern __shared__ float dsm[];
    float* sx  = dsm;               // 32 x 34 padded   = 1088
    float* sa1 = dsm + 1088;        // 32 x 15 x 18     = 8640
    float* swb = sa1 + 8640;        // 9216 ([ic][oc][k], reused w2 -> w3)
    float* sa2 = swb + 9216;        // 32 x 6 x 8       = 1536
    __shared__ float sw1[288];
    __shared__ float sc1s[32], sc1h[32], sc2s[32], sc2h[32], sc3s[32], sc3h[32];

    int b = blockIdx.x, tid = threadIdx.x;

    const float* xin = x + b * 1024;
    for (int i = tid; i < 1024; i += 288) {
        int row = i >> 5, col = i & 31;
        sx[row * 34 + col] = xin[i];
    }
    if (tid < 288) sw1[tid] = w1[tid];
    for (int i = tid; i < 9216; i += 288) {
        int oc = i / 288, rem = i - oc * 288, ic = rem / 9, k = rem - ic * 9;
        swb[(ic * 32 + oc) * 9 + k] = w2[i];
    }
    if (tid < 32) {
        float inv = g1[tid] * rsqrtf(v1[tid] + 1e-5f);
        sc1s[tid] = inv; sc1h[tid] = bb1[tid] - m1[tid] * inv + cb1[tid] * inv;
        inv = g2[tid] * rsqrtf(v2[tid] + 1e-5f);
        sc2s[tid] = inv; sc2h[tid] = bb2[tid] - m2[tid] * inv + cb2[tid] * inv;
        inv = g3[tid] * rsqrtf(v3[tid] + 1e-5f);
        sc3s[tid] = inv; sc3h[tid] = bb3[tid] - m3[tid] * inv + cb3[tid] * inv;
    }
    __syncthreads();

    // ---- conv1 ----
    for (int i = tid; i < 7200; i += 288) {
        int c = i / 225, p = i - c * 225, py = p / 15, px = p - py * 15;
        const float* wc = sw1 + c * 9;
        const float* ip = sx + (2 * py) * 34 + 2 * px;
        float r[4][4];
        #pragma unroll
        for (int rr = 0; rr < 4; rr++) {
            float2 a = *(const float2*)(ip + rr * 34);
            float2 q = *(const float2*)(ip + rr * 34 + 2);
            r[rr][0] = a.x; r[rr][1] = a.y; r[rr][2] = q.x; r[rr][3] = q.y;
        }
        float s00 = 0.f, s01 = 0.f, s10 = 0.f, s11 = 0.f;
        #pragma unroll
        for (int ky = 0; ky < 3; ky++)
            #pragma unroll
            for (int kx = 0; kx < 3; kx++) {
                float wv = wc[ky * 3 + kx];
                s00 += r[ky][kx]     * wv;  s01 += r[ky][kx + 1]     * wv;
                s10 += r[ky + 1][kx] * wv;  s11 += r[ky + 1][kx + 1] * wv;
            }
        float sc = sc1s[c], sh = sc1h[c];
        sa1[(c * 15 + py) * 18 + px] = 0.25f *
            (fmaxf(s00 * sc + sh, 0.f) + fmaxf(s01 * sc + sh, 0.f) +
             fmaxf(s10 * sc + sh, 0.f) + fmaxf(s11 * sc + sh, 0.f));
    }
    __syncthreads();

    // ---- conv2: thread = 4 oc x 1 pooled pos ----
    {
        int ocg = tid / 36;
        int p = tid - ocg * 36, py = p / 6, px = p - py * 6;
        float s[4][4];
        #pragma unroll
        for (int a = 0; a < 4; a++)
            #pragma unroll
            for (int q = 0; q < 4; q++) s[a][q] = 0.f;
        for (int ic = 0; ic < 32; ic++) {
            const float* ip = sa1 + (ic * 15 + 2 * py) * 18 + 2 * px;
            float r[4][4];
            #pragma unroll
            for (int rr = 0; rr < 4; rr++) {
                float2 a = *(const float2*)(ip + rr * 18);
                float2 q = *(const float2*)(ip + rr * 18 + 2);
                r[rr][0] = a.x; r[rr][1] = a.y; r[rr][2] = q.x; r[rr][3] = q.y;
            }
            const float* wb = swb + (ic * 32 + ocg * 4) * 9;
            #pragma unroll
            for (int o4 = 0; o4 < 4; o4++) {
                const float* wp = wb + o4 * 9;
                #pragma unroll
                for (int ky = 0; ky < 3; ky++)
                    #pragma unroll
                    for (int kx = 0; kx < 3; kx++) {
                        float wv = wp[ky * 3 + kx];
                        s[o4][0] += r[ky][kx]     * wv;  s[o4][1] += r[ky][kx + 1]     * wv;
                        s[o4][2] += r[ky + 1][kx] * wv;  s[o4][3] += r[ky + 1][kx + 1] * wv;
                    }
            }
        }
        #pragma unroll
        for (int o4 = 0; o4 < 4; o4++) {
            int oc = ocg * 4 + o4;
            float sc = sc2s[oc], sh = sc2h[oc];
            sa2[(oc * 6 + py) * 8 + px] = 0.25f *
                (fmaxf(s[o4][0] * sc + sh, 0.f) + fmaxf(s[o4][1] * sc + sh, 0.f) +
                 fmaxf(s[o4][2] * sc + sh, 0.f) + fmaxf(s[o4][3] * sc + sh, 0.f));
        }
    }
    __syncthreads();

    for (int i = tid; i < 9216; i += 288) {
        int oc = i / 288, rem = i - oc * 288, ic = rem / 9, k = rem - ic * 9;
        swb[(ic * 32 + oc) * 9 + k] = w3[i];
    }
    __syncthreads();

    // ---- conv3 -> feat ----
    if (tid < 128) {
        int c = tid >> 2, q = tid & 3, y = q >> 1, xx = q & 1;
        float s00 = 0.f, s01 = 0.f, s10 = 0.f, s11 = 0.f;
        for (int ic = 0; ic < 32; ic++) {
            const float* ip = sa2 + (ic * 6 + 2 * y) * 8 + 2 * xx;
            float r[4][4];
            #pragma unroll
            for (int rr = 0; rr < 4; rr++) {
                float2 a = *(const float2*)(ip + rr * 8);
                float2 qq = *(const float2*)(ip + rr * 8 + 2);
                r[rr][0] = a.x; r[rr][1] = a.y; r[rr][2] = qq.x; r[rr][3] = qq.y;
            }
            const float* wp = swb + (ic * 32 + c) * 9;
            #pragma unroll
            for (int ky = 0; ky < 3; ky++)
                #pragma unroll
                for (int kx = 0; kx < 3; kx++) {
                    float wv = wp[ky * 3 + kx];
                    s00 += r[ky][kx]     * wv;  s01 += r[ky][kx + 1]     * wv;
                    s10 += r[ky + 1][kx] * wv;  s11 += r[ky + 1][kx + 1] * wv;
                }
        }
        float sc = sc3s[c], sh = sc3h[c];
        g_feat[b * 128 + tid] = 0.25f *
            (fmaxf(s00 * sc + sh, 0.f) + fmaxf(s01 * sc + sh, 0.f) +
             fmaxf(s10 * sc + sh, 0.f) + fmaxf(s11 * sc + sh, 0.f));
    }
}

// =====================================================================
// Beam search router. 1 block / sample. Writes g_ops.
// =====================================================================
__global__ void __launch_bounds__(256)
k_beam(const float* __restrict__ Whh, const float* __restrict__ bh,
       const float* __restrict__ Who, const float* __restrict__ bo)
{
    __shared__ float shr[2][1024];
    __shared__ float sexh[384], sWho[384], sbh[128], sbo[3];
    __shared__ float slog[24], stotal[24];
    __shared__ float nscore[8], sscore[8];
    __shared__ int   nbeam[8], nop[8], sops[2][3][8];

    int b = blockIdx.x, tid = threadIdx.x;
    int warp = tid >> 5, lane = tid & 31;

    for (int i = tid; i < 384; i += 256) { sWho[i] = Who[i]; sexh[i] = g_exh[i]; }
    if (tid < 128) sbh[tid] = bh[tid];
    if (tid < 3)   sbo[tid] = bo[tid];
    if (tid < 8)   sscore[tid] = (tid == 0) ? 0.f : NEG;
    for (int i = tid; i < 1024; i += 256) shr[0][i] = g_feat[b * 128 + (i & 127)];
    __syncthreads();

    int cur = 0;
    for (int t = 0; t < 3; t++) {
        // logits[k][o] = hr[k] . Who[:,o] + bo[o]   (warp k)
        {
            const float* h = shr[0] + warp * 128;
            float a0 = 0.f, a1 = 0.f, a2 = 0.f;
            for (int d = lane; d < 128; d += 32) {
                float hv = h[d];
                a0 += hv * sWho[d * 3 + 0];
                a1 += hv * sWho[d * 3 + 1];
                a2 += hv * sWho[d * 3 + 2];
            }
            #pragma unroll
            for (int off = 16; off; off >>= 1) {
                a0 += __shfl_xor_sync(0xffffffffu, a0, off);
                a1 += __shfl_xor_sync(0xffffffffu, a1, off);
                a2 += __shfl_xor_sync(0xffffffffu, a2, off);
            }
            if (lane == 0) {
                slog[warp * 3 + 0] = a0 + sbo[0];
                slog[warp * 3 + 1] = a1 + sbo[1];
                slog[warp * 3 + 2] = a2 + sbo[2];
            }
        }
        __syncthreads();
        if (tid < 8) {
            float y0 = slog[tid * 3 + 0] * 2.5f;
            float y1 = slog[tid * 3 + 1] * 2.5f;
            float y2 = slog[tid * 3 + 2] * 2.5f;
            float mx = fmaxf(y0, fmaxf(y1, y2));
            float lse = logf(expf(y0 - mx) + expf(y1 - mx) + expf(y2 - mx));
            float sc = sscore[tid];
            stotal[tid * 3 + 0] = sc + (y0 - mx - lse);
            stotal[tid * 3 + 1] = sc + (y1 - mx - lse);
            stotal[tid * 3 + 2] = sc + (y2 - mx - lse);
        }
        __syncthreads();
        // stable top-8 of 24 (lower index wins ties == lax.top_k)
        if (tid < 24) {
            float v = stotal[tid];
            int rank = 0;
            #pragma unroll
            for (int j = 0; j < 24; j++) {
                float u = stotal[j];
                rank += (u > v) || (u == v && j < tid);
            }
            if (rank < 8) { nscore[rank] = v; nbeam[rank] = tid / 3; nop[rank] = tid % 3; }
        }
        __syncthreads();
        for (int i = tid; i < 1024; i += 256) {
            int k = i >> 7;
            shr[1][i] = shr[0][nbeam[k] * 128 + (i & 127)];
        }
        if (tid < 8) {
            sscore[tid] = nscore[tid];
            for (int s = 0; s < t; s++) sops[1 - cur][s][tid] = sops[cur][s][nbeam[tid]];
            sops[1 - cur][t][tid] = nop[tid];
        }
        __syncthreads();
        cur ^= 1;
        // hr = tanh(hr_sel @ Whh + exh[op] + bh) : warp w -> beams {2w,2w+1}
        if (warp < 4) {
            int r0 = warp * 2, r1 = r0 + 1;
            const float* h0 = shr[1] + r0 * 128;
            const float* h1 = shr[1] + r1 * 128;
            float4 a0 = make_float4(0.f, 0.f, 0.f, 0.f);
            float4 a1 = make_float4(0.f, 0.f, 0.f, 0.f);
            #pragma unroll 8
            for (int d = 0; d < 128; d++) {
                float4 w4 = *(const float4*)(Whh + d * 128 + 4 * lane);
                float v0 = h0[d], v1 = h1[d];
                a0.x += v0 * w4.x; a0.y += v0 * w4.y; a0.z += v0 * w4.z; a0.w += v0 * w4.w;
                a1.x += v1 * w4.x; a1.y += v1 * w4.y; a1.z += v1 * w4.z; a1.w += v1 * w4.w;
            }
            int j = 4 * lane;
            int o0 = nop[r0], o1 = nop[r1];
            const float* e0 = sexh + o0 * 128;
            const float* e1 = sexh + o1 * 128;
            float* d0 = shr[0] + r0 * 128;
            float* d1 = shr[0] + r1 * 128;
            d0[j + 0] = tanhf(a0.x + e0[j + 0] + sbh[j + 0]);
            d0[j + 1] = tanhf(a0.y + e0[j + 1] + sbh[j + 1]);
            d0[j + 2] = tanhf(a0.z + e0[j + 2] + sbh[j + 2]);
            d0[j + 3] = tanhf(a0.w + e0[j + 3] + sbh[j + 3]);
            d1[j + 0] = tanhf(a1.x + e1[j + 0] + sbh[j + 0]);
            d1[j + 1] = tanhf(a1.y + e1[j + 1] + sbh[j + 1]);
            d1[j + 2] = tanhf(a1.z + e1[j + 2] + sbh[j + 2]);
            d1[j + 3] = tanhf(a1.w + e1[j + 3] + sbh[j + 3]);
        }
        __syncthreads();
    }
    if (tid < 8) {
        #pragma unroll
        for (int s = 0; s < 3; s++) g_ops[(b * 8 + tid) * 3 + s] = sops[cur][s][tid];
    }
}

// =====================================================================
// Expert chain + classifier. 4 rows/block, 2 warps/row (d-split 64/64).
// grid = 1024 x 256 threads -> 8192 warps total.
// =====================================================================
__global__ void __launch_bounds__(256)
k_expert(const float* __restrict__ Wexp, const float* __restrict__ bexp,
         const float* __restrict__ Wout, const float* __restrict__ bout,
         float* __restrict__ out)
{
    __shared__ float h[4][128];
    __shared__ float part[4][128];

    int tid = threadIdx.x;
    int warp = tid >> 5, lane = tid & 31;
    int r = warp >> 1;                  // local row 0..3
    int half = warp & 1;                // d-half
    int row = blockIdx.x * 4 + r;       // global row = b*8 + beam
    int b = row >> 3;
    int j = 4 * lane;

    // load feat
    h[r][half * 64 + lane]      = g_feat[b * 128 + half * 64 + lane];
    h[r][half * 64 + lane + 32] = g_feat[b * 128 + half * 64 + lane + 32];
    __syncthreads();

    #pragma unroll
    for (int t = 0; t < 3; t++) {
        int o = g_ops[row * 3 + t];
        const float* W = Wexp + o * 16384 + half * 64 * 128;
        const float* hh = h[r] + half * 64;
        float4 acc = make_float4(0.f, 0.f, 0.f, 0.f);
        #pragma unroll 8
        for (int d = 0; d < 64; d++) {
            float hv = hh[d];
            float4 w4 = *(const float4*)(W + d * 128 + j);
            acc.x += hv * w4.x; acc.y += hv * w4.y;
            acc.z += hv * w4.z; acc.w += hv * w4.w;
        }
        if (half == 1) {
            part[r][j + 0] = acc.x; part[r][j + 1] = acc.y;
            part[r][j + 2] = acc.z; part[r][j + 3] = acc.w;
        }
        __syncthreads();
        if (half == 0) {
            float4 bb = *(const float4*)(bexp + o * 128 + j);
            h[r][j + 0] = fmaxf(acc.x + part[r][j + 0] + bb.x, 0.f);
            h[r][j + 1] = fmaxf(acc.y + part[r][j + 1] + bb.y, 0.f);
            h[r][j + 2] = fmaxf(acc.z + part[r][j + 2] + bb.z, 0.f);
            h[r][j + 3] = fmaxf(acc.w + part[r][j + 3] + bb.w, 0.f);
        }
        __syncthreads();
    }

    // final 128->10 + log_softmax, by half-0 warp of each row
    if (half == 0) {
        const float* hh = h[r];
        float logit = NEG;
        if (lane < 10) {
            float acc = bout[lane];
            #pragma unroll 8
            for (int d = 0; d < 128; d++) acc += hh[d] * Wout[d * 10 + lane];
            logit = acc;
        }
        float mx = logit;
        #pragma unroll
        for (int off = 8; off; off >>= 1)
            mx = fmaxf(mx, __shfl_xor_sync(0xffffffffu, mx, off, 16));
        float p = (lane < 10) ? expf(logit - mx) : 0.f;
        float s = p;
        #pragma unroll
        for (int off = 8; off; off >>= 1)
            s += __shfl_xor_sync(0xffffffffu, s, off, 16);
        if (lane < 10) out[row * 10 + lane] = logit - mx - logf(s);
    }
}

// ---------------- launcher ----------------
extern "C" void kernel_launch(void* const* d_in, const int* in_sizes, int n_in,
                              void* d_out, int out_size)
{
    const float* x       = (const float*)d_in[0];
    const float* conv1_w = (const float*)d_in[1];
    const float* conv1_b = (const float*)d_in[2];
    const float* bn1_g   = (const float*)d_in[3];
    const float* bn1_b   = (const float*)d_in[4];
    const float* bn1_m   = (const float*)d_in[5];
    const float* bn1_v   = (const float*)d_in[6];
    const float* conv2_w = (const float*)d_in[7];
    const float* conv2_b = (const float*)d_in[8];
    const float* bn2_g   = (const float*)d_in[9];
    const float* bn2_b   = (const float*)d_in[10];
    const float* bn2_m   = (const float*)d_in[11];
    const float* bn2_v   = (const float*)d_in[12];
    const float* conv3_w = (const float*)d_in[13];
    const float* conv3_b = (const float*)d_in[14];
    const float* bn3_g   = (const float*)d_in[15];
    const float* bn3_b   = (const float*)d_in[16];
    const float* bn3_m   = (const float*)d_in[17];
    const float* bn3_v   = (const float*)d_in[18];
    const float* Wxh     = (const float*)d_in[19];
    const float* Whh     = (const float*)d_in[20];
    const float* bh      = (const float*)d_in[21];
    const float* Who     = (const float*)d_in[22];
    const float* bo      = (const float*)d_in[23];
    const float* emb     = (const float*)d_in[24];
    const float* Wexp    = (const float*)d_in[25];
    const float* bexp    = (const float*)d_in[26];
    const float* Wout    = (const float*)d_in[27];
    const float* bout    = (const float*)d_in[28];
    float* out = (float*)d_out;

    cudaFuncSetAttribute(k_conv_all, cudaFuncAttributeMaxDynamicSharedMemorySize, 81920);

    k_exh<<<1, 384>>>(emb, Wxh);
    k_conv_all<<<BATCH, 288, 81920>>>(x,
        conv1_w, conv1_b, bn1_g, bn1_b, bn1_m, bn1_v,
        conv2_w, conv2_b, bn2_g, bn2_b, bn2_m, bn2_v,
        conv3_w, conv3_b, bn3_g, bn3_b, bn3_m, bn3_v);
    k_beam<<<BATCH, 256>>>(Whh, bh, Who, bo);
    k_expert<<<BATCH * 2, 256>>>(Wexp, bexp, Wout, bout, out);
}

// round 4
// speedup vs baseline: 1.0227x; 1.0227x over previous
#include <cuda_runtime.h>
#include <math.h>

#define BATCH 512
#define NEG   (-1e9f)

typedef unsigned long long u64;

__device__ __forceinline__ u64 pk2(float lo, float hi) {
    u64 r; asm("mov.b64 %0, {%1,%2};" : "=l"(r) : "f"(lo), "f"(hi)); return r;
}
__device__ __forceinline__ void fma2(u64& d, u64 a, u64 b) {
    asm("fma.rn.f32x2 %0, %1, %2, %3;" : "=l"(d) : "l"(a), "l"(b), "l"(d));
}
__device__ __forceinline__ void unpk2(u64 v, float& a, float& b) {
    asm("mov.b64 {%0,%1}, %2;" : "=f"(a), "=f"(b) : "l"(v));
}

// ---------------- scratch ----------------
__device__ float g_feat[BATCH * 128];
__device__ int   g_ops[BATCH * 8 * 3];

// =====================================================================
// Fused conv1+conv2+conv3 (+BN+ReLU+pool each) per image.
// =====================================================================
__global__ void __launch_bounds__(288, 2)
k_conv_all(const float* __restrict__ x,
           const float* __restrict__ w1, const float* __restrict__ cb1,
           const float* __restrict__ g1, const float* __restrict__ bb1,
           const float* __restrict__ m1, const float* __restrict__ v1,
           const float* __restrict__ w2, const float* __restrict__ cb2,
           const float* __restrict__ g2, const float* __restrict__ bb2,
           const float* __restrict__ m2, const float* __restrict__ v2,
           const float* __restrict__ w3, const float* __restrict__ cb3,
           const float* __restrict__ g3, const float* __restrict__ bb3,
           const float* __restrict__ m3, const float* __restrict__ v3)
{
    extern __shared__ float dsm[];
    float* sx  = dsm;               // 32 x 34
    float* sa1 = dsm + 1088;        // 32 x 15 x 18
    float* swb = sa1 + 8640;        // 9216 ([ic][oc][k])
    float* sa2 = swb + 9216;        // 32 x 6 x 8
    __shared__ float sw1[288];
    __shared__ float sc1s[32], sc1h[32], sc2s[32], sc2h[32], sc3s[32], sc3h[32];

    int b = blockIdx.x, tid = threadIdx.x;

    const float* xin = x + b * 1024;
    for (int i = tid; i < 1024; i += 288) {
        int row = i >> 5, col = i & 31;
        sx[row * 34 + col] = xin[i];
    }
    if (tid < 288) sw1[tid] = w1[tid];
    for (int i = tid; i < 9216; i += 288) {
        int oc = i / 288, rem = i - oc * 288, ic = rem / 9, k = rem - ic * 9;
        swb[(ic * 32 + oc) * 9 + k] = w2[i];
    }
    if (tid < 32) {
        float inv = g1[tid] * rsqrtf(v1[tid] + 1e-5f);
        sc1s[tid] = inv; sc1h[tid] = bb1[tid] - m1[tid] * inv + cb1[tid] * inv;
        inv = g2[tid] * rsqrtf(v2[tid] + 1e-5f);
        sc2s[tid] = inv; sc2h[tid] = bb2[tid] - m2[tid] * inv + cb2[tid] * inv;
        inv = g3[tid] * rsqrtf(v3[tid] + 1e-5f);
        sc3s[tid] = inv; sc3h[tid] = bb3[tid] - m3[tid] * inv + cb3[tid] * inv;
    }
    __syncthreads();

    // ---- conv1 ----
    for (int i = tid; i < 7200; i += 288) {
        int c = i / 225, p = i - c * 225, py = p / 15, px = p - py * 15;
        const float* wc = sw1 + c * 9;
        const float* ip = sx + (2 * py) * 34 + 2 * px;
        float r[4][4];
        #pragma unroll
        for (int rr = 0; rr < 4; rr++) {
            float2 a = *(const float2*)(ip + rr * 34);
            float2 q = *(const float2*)(ip + rr * 34 + 2);
            r[rr][0] = a.x; r[rr][1] = a.y; r[rr][2] = q.x; r[rr][3] = q.y;
        }
        float s00 = 0.f, s01 = 0.f, s10 = 0.f, s11 = 0.f;
        #pragma unroll
        for (int ky = 0; ky < 3; ky++)
            #pragma unroll
            for (int kx = 0; kx < 3; kx++) {
                float wv = wc[ky * 3 + kx];
                s00 += r[ky][kx]     * wv;  s01 += r[ky][kx + 1]     * wv;
                s10 += r[ky + 1][kx] * wv;  s11 += r[ky + 1][kx + 1] * wv;
            }
        float sc = sc1s[c], sh = sc1h[c];
        sa1[(c * 15 + py) * 18 + px] = 0.25f *
            (fmaxf(s00 * sc + sh, 0.f) + fmaxf(s01 * sc + sh, 0.f) +
             fmaxf(s10 * sc + sh, 0.f) + fmaxf(s11 * sc + sh, 0.f));
    }
    __syncthreads();

    // ---- conv2: thread = 4 oc x 1 pooled pos, f32x2-packed FMA ----
    {
        int ocg = tid / 36;
        int p = tid - ocg * 36, py = p / 6, px = p - py * 6;
        u64 acc[4][2];
        #pragma unroll
        for (int a = 0; a < 4; a++) { acc[a][0] = 0ull; acc[a][1] = 0ull; }
        for (int ic = 0; ic < 32; ic++) {
            const float* ip = sa1 + (ic * 15 + 2 * py) * 18 + 2 * px;
            float r[4][4];
            #pragma unroll
            for (int rr = 0; rr < 4; rr++) {
                float2 a = *(const float2*)(ip + rr * 18);
                float2 q = *(const float2*)(ip + rr * 18 + 2);
                r[rr][0] = a.x; r[rr][1] = a.y; r[rr][2] = q.x; r[rr][3] = q.y;
            }
            u64 rp[4][3];
            #pragma unroll
            for (int rr = 0; rr < 4; rr++)
                #pragma unroll
                for (int kx = 0; kx < 3; kx++)
                    rp[rr][kx] = pk2(r[rr][kx], r[rr][kx + 1]);
            const float* wb = swb + (ic * 32 + ocg * 4) * 9;
            #pragma unroll
            for (int o4 = 0; o4 < 4; o4++) {
                const float* wp = wb + o4 * 9;
                #pragma unroll
                for (int ky = 0; ky < 3; ky++)
                    #pragma unroll
                    for (int kx = 0; kx < 3; kx++) {
                        float wv = wp[ky * 3 + kx];
                        u64 w2d = pk2(wv, wv);
                        fma2(acc[o4][0], rp[ky][kx],     w2d);
                        fma2(acc[o4][1], rp[ky + 1][kx], w2d);
                    }
            }
        }
        #pragma unroll
        for (int o4 = 0; o4 < 4; o4++) {
            int oc = ocg * 4 + o4;
            float sc = sc2s[oc], sh = sc2h[oc];
            float s00, s01, s10, s11;
            unpk2(acc[o4][0], s00, s01);
            unpk2(acc[o4][1], s10, s11);
            sa2[(oc * 6 + py) * 8 + px] = 0.25f *
                (fmaxf(s00 * sc + sh, 0.f) + fmaxf(s01 * sc + sh, 0.f) +
                 fmaxf(s10 * sc + sh, 0.f) + fmaxf(s11 * sc + sh, 0.f));
        }
    }
    __syncthreads();

    for (int i = tid; i < 9216; i += 288) {
        int oc = i / 288, rem = i - oc * 288, ic = rem / 9, k = rem - ic * 9;
        swb[(ic * 32 + oc) * 9 + k] = w3[i];
    }
    __syncthreads();

    // ---- conv3 -> feat ----
    if (tid < 128) {
        int c = tid >> 2, q = tid & 3, y = q >> 1, xx = q & 1;
        float s00 = 0.f, s01 = 0.f, s10 = 0.f, s11 = 0.f;
        for (int ic = 0; ic < 32; ic++) {
            const float* ip = sa2 + (ic * 6 + 2 * y) * 8 + 2 * xx;
            float r[4][4];
            #pragma unroll
            for (int rr = 0; rr < 4; rr++) {
                float2 a = *(const float2*)(ip + rr * 8);
                float2 qq = *(const float2*)(ip + rr * 8 + 2);
                r[rr][0] = a.x; r[rr][1] = a.y; r[rr][2] = qq.x; r[rr][3] = qq.y;
            }
            const float* wp = swb + (ic * 32 + c) * 9;
            #pragma unroll
            for (int ky = 0; ky < 3; ky++)
                #pragma unroll
                for (int kx = 0; kx < 3; kx++) {
                    float wv = wp[ky * 3 + kx];
                    s00 += r[ky][kx]     * wv;  s01 += r[ky][kx + 1]     * wv;
                    s10 += r[ky + 1][kx] * wv;  s11 += r[ky + 1][kx + 1] * wv;
                }
        }
        float sc = sc3s[c], sh = sc3h[c];
        g_feat[b * 128 + tid] = 0.25f *
            (fmaxf(s00 * sc + sh, 0.f) + fmaxf(s01 * sc + sh, 0.f) +
             fmaxf(s10 * sc + sh, 0.f) + fmaxf(s11 * sc + sh, 0.f));
    }
}

// =====================================================================
// Beam search (exh inline). 1 block / sample, 8 warps = 4 pairs x 2 d-halves.
// =====================================================================
__global__ void __launch_bounds__(256)
k_beam(const float* __restrict__ Whh, const float* __restrict__ bh,
       const float* __restrict__ Who, const float* __restrict__ bo,
       const float* __restrict__ emb, const float* __restrict__ Wxh)
{
    __shared__ float shr[2][1024];
    __shared__ float part[8][128];
    __shared__ float sexh[384], sWho[384], sbh[128], sbo[3];
    __shared__ float slog[24], stotal[24];
    __shared__ float nscore[8], sscore[8];
    __shared__ int   nbeam[8], nop[8], sops[2][3][8];

    int b = blockIdx.x, tid = threadIdx.x;
    int warp = tid >> 5, lane = tid & 31;

    for (int i = tid; i < 384; i += 256) sWho[i] = Who[i];
    if (tid < 128) sbh[tid] = bh[tid];
    if (tid < 3)   sbo[tid] = bo[tid];
    if (tid < 8)   sscore[tid] = (tid == 0) ? 0.f : NEG;
    for (int i = tid; i < 1024; i += 256) shr[0][i] = g_feat[b * 128 + (i & 127)];
    // exh = emb @ Wxh (3x128), per-block
    for (int i = tid; i < 384; i += 256) {
        int o = i >> 7, j = i & 127;
        float acc = 0.f;
        #pragma unroll 4
        for (int d = 0; d < 128; d++) acc += emb[o * 128 + d] * Wxh[d * 128 + j];
        sexh[i] = acc;
    }
    __syncthreads();

    int cur = 0;
    for (int t = 0; t < 3; t++) {
        // logits[k][o] = hr[k] . Who[:,o] + bo[o]   (warp k)
        {
            const float* h = shr[0] + warp * 128;
            float a0 = 0.f, a1 = 0.f, a2 = 0.f;
            for (int d = lane; d < 128; d += 32) {
                float hv = h[d];
                a0 += hv * sWho[d * 3 + 0];
                a1 += hv * sWho[d * 3 + 1];
                a2 += hv * sWho[d * 3 + 2];
            }
            #pragma unroll
            for (int off = 16; off; off >>= 1) {
                a0 += __shfl_xor_sync(0xffffffffu, a0, off);
                a1 += __shfl_xor_sync(0xffffffffu, a1, off);
                a2 += __shfl_xor_sync(0xffffffffu, a2, off);
            }
            if (lane == 0) {
                slog[warp * 3 + 0] = a0 + sbo[0];
                slog[warp * 3 + 1] = a1 + sbo[1];
                slog[warp * 3 + 2] = a2 + sbo[2];
            }
        }
        __syncthreads();
        if (tid < 8) {
            float y0 = slog[tid * 3 + 0] * 2.5f;
            float y1 = slog[tid * 3 + 1] * 2.5f;
            float y2 = slog[tid * 3 + 2] * 2.5f;
            float mx = fmaxf(y0, fmaxf(y1, y2));
            float lse = logf(expf(y0 - mx) + expf(y1 - mx) + expf(y2 - mx));
            float sc = sscore[tid];
            stotal[tid * 3 + 0] = sc + (y0 - mx - lse);
            stotal[tid * 3 + 1] = sc + (y1 - mx - lse);
            stotal[tid * 3 + 2] = sc + (y2 - mx - lse);
        }
        __syncthreads();
        // stable top-8 of 24 (lower index wins ties == lax.top_k)
        if (tid < 24) {
            float v = stotal[tid];
            int rank = 0;
            #pragma unroll
            for (int j = 0; j < 24; j++) {
                float u = stotal[j];
                rank += (u > v) || (u == v && j < tid);
            }
            if (rank < 8) { nscore[rank] = v; nbeam[rank] = tid / 3; nop[rank] = tid % 3; }
        }
        __syncthreads();
        for (int i = tid; i < 1024; i += 256) {
            int k = i >> 7;
            shr[1][i] = shr[0][nbeam[k] * 128 + (i & 127)];
        }
        if (tid < 8) {
            sscore[tid] = nscore[tid];
            for (int s = 0; s < t; s++) sops[1 - cur][s][tid] = sops[cur][s][nbeam[tid]];
            sops[1 - cur][t][tid] = nop[tid];
        }
        __syncthreads();
        cur ^= 1;
        // hr = tanh(hr_sel @ Whh + exh[op] + bh)
        // warp = pair(0..3) + half(d-split): beams {2p, 2p+1}
        {
            int pair = warp & 3, half = warp >> 2;
            int r0 = 2 * pair, r1 = r0 + 1;
            const float* h0 = shr[1] + r0 * 128 + half * 64;
            const float* h1 = shr[1] + r1 * 128 + half * 64;
            const float* Wb = Whh + half * 64 * 128 + 4 * lane;
            float4 a0 = make_float4(0.f, 0.f, 0.f, 0.f);
            float4 a1 = make_float4(0.f, 0.f, 0.f, 0.f);
            #pragma unroll 8
            for (int d = 0; d < 64; d++) {
                float4 w4 = *(const float4*)(Wb + d * 128);
                float v0 = h0[d], v1 = h1[d];
                a0.x += v0 * w4.x; a0.y += v0 * w4.y; a0.z += v0 * w4.z; a0.w += v0 * w4.w;
                a1.x += v1 * w4.x; a1.y += v1 * w4.y; a1.z += v1 * w4.z; a1.w += v1 * w4.w;
            }
            int j = 4 * lane;
            if (half == 1) {
                part[r0][j + 0] = a0.x; part[r0][j + 1] = a0.y;
                part[r0][j + 2] = a0.z; part[r0][j + 3] = a0.w;
                part[r1][j + 0] = a1.x; part[r1][j + 1] = a1.y;
                part[r1][j + 2] = a1.z; part[r1][j + 3] = a1.w;
            }
            __syncthreads();
            if (half == 0) {
                int o0 = nop[r0], o1 = nop[r1];
                const float* e0 = sexh + o0 * 128;
                const float* e1 = sexh + o1 * 128;
                float* d0 = shr[0] + r0 * 128;
                float* d1 = shr[0] + r1 * 128;
                d0[j + 0] = tanhf(a0.x + part[r0][j + 0] + e0[j + 0] + sbh[j + 0]);
                d0[j + 1] = tanhf(a0.y + part[r0][j + 1] + e0[j + 1] + sbh[j + 1]);
                d0[j + 2] = tanhf(a0.z + part[r0][j + 2] + e0[j + 2] + sbh[j + 2]);
                d0[j + 3] = tanhf(a0.w + part[r0][j + 3] + e0[j + 3] + sbh[j + 3]);
                d1[j + 0] = tanhf(a1.x + part[r1][j + 0] + e1[j + 0] + sbh[j + 0]);
                d1[j + 1] = tanhf(a1.y + part[r1][j + 1] + e1[j + 1] + sbh[j + 1]);
                d1[j + 2] = tanhf(a1.z + part[r1][j + 2] + e1[j + 2] + sbh[j + 2]);
                d1[j + 3] = tanhf(a1.w + part[r1][j + 3] + e1[j + 3] + sbh[j + 3]);
            }
            __syncthreads();
        }
    }
    if (tid < 8) {
        #pragma unroll
        for (int s = 0; s < 3; s++) g_ops[(b * 8 + tid) * 3 + s] = sops[cur][s][tid];
    }
}

// =====================================================================
// Expert chain: smem-resident weights (all 3), rows grouped by op.
// 128 blocks x 32 rows, 256 threads, 192KB dyn smem.
// =====================================================================
#define EROWS 32
__global__ void __launch_bounds__(256)
k_expert(const float* __restrict__ Wexp, const float* __restrict__ bexp,
         const float* __restrict__ Wout, const float* __restrict__ bout,
         float* __restrict__ out)
{
    extern __shared__ float sw[];          // 49152 floats = 192 KB
    __shared__ float hgt[128][40];         // transposed, group-ordered h
    __shared__ float sbias[384];
    __shared__ int sop[EROWS * 3];
    __shared__ int gperm[3][40];
    __shared__ int gop[3][10];
    __shared__ int slotOf[4][EROWS];
    __shared__ int sng[3];

    int tid = threadIdx.x, warp = tid >> 5, lane = tid & 31;
    int rowbase = blockIdx.x * EROWS;

    for (int i = tid; i < 49152; i += 256) sw[i] = Wexp[i];
    for (int i = tid; i < 384; i += 256) sbias[i] = bexp[i];
    if (tid < EROWS * 3) sop[tid] = g_ops[rowbase * 3 + tid];
    for (int i = tid; i < 128 * 40; i += 256) (&hgt[0][0])[i] = 0.f;
    __syncthreads();

    if (tid == 0) {
        for (int t = 0; t < 3; t++) {
            int cnt[3] = {0, 0, 0};
            int lists[3][EROWS];
            for (int j = 0; j < EROWS; j++) {
                int o = sop[j * 3 + t];
                lists[o][cnt[o]++] = j;
            }
            int g = 0;
            for (int o = 0; o < 3; o++)
                for (int base = 0; base < cnt[o]; base += 4) {
                    gop[t][g] = o;
                    for (int k = 0; k < 4; k++) {
                        int idx = base + k;
                        int r = (idx < cnt[o]) ? lists[o][idx] : -1;
                        gperm[t][g * 4 + k] = r;
                        if (r >= 0) slotOf[t][r] = g * 4 + k;
                    }
                    g++;
                }
            sng[t] = g;
        }
        for (int j = 0; j < EROWS; j++) slotOf[3][j] = j;
    }
    __syncthreads();

    // feat -> layer-0 slots
    for (int i = tid; i < EROWS * 128; i += 256) {
        int lr = i >> 7, d = i & 127;
        hgt[d][slotOf[0][lr]] = g_feat[((rowbase + lr) >> 3) * 128 + d];
    }
    __syncthreads();

    for (int t = 0; t < 3; t++) {
        int ng = sng[t];
        u64 A[2][8];
        #pragma unroll
        for (int rd = 0; rd < 2; rd++)
            #pragma unroll
            for (int z = 0; z < 8; z++) A[rd][z] = 0ull;

        #pragma unroll
        for (int rd = 0; rd < 2; rd++) {
            int g = warp + rd * 8;
            if (g >= ng) continue;
            const float* W = sw + gop[t][g] * 16384 + 4 * lane;
            #pragma unroll 4
            for (int d = 0; d < 128; d++) {
                float4 w4 = *(const float4*)(W + d * 128);
                float4 hv = *(const float4*)(&hgt[d][4 * g]);
                u64 wa = pk2(w4.x, w4.y), wb = pk2(w4.z, w4.w);
                u64 hx = pk2(hv.x, hv.x), hy = pk2(hv.y, hv.y);
                u64 hz = pk2(hv.z, hv.z), hw = pk2(hv.w, hv.w);
                fma2(A[rd][0], wa, hx); fma2(A[rd][1], wb, hx);
                fma2(A[rd][2], wa, hy); fma2(A[rd][3], wb, hy);
                fma2(A[rd][4], wa, hz); fma2(A[rd][5], wb, hz);
                fma2(A[rd][6], wa, hw); fma2(A[rd][7], wb, hw);
            }
        }
        __syncthreads();
        #pragma unroll
        for (int rd = 0; rd < 2; rd++) {
            int g = warp + rd * 8;
            if (g >= ng) continue;
            int o = gop[t][g];
            int j = 4 * lane;
            float b0 = sbias[o * 128 + j], b1 = sbias[o * 128 + j + 1];
            float b2 = sbias[o * 128 + j + 2], b3 = sbias[o * 128 + j + 3];
            #pragma unroll
            for (int k = 0; k < 4; k++) {
                int r = gperm[t][g * 4 + k];
                if (r < 0) continue;
                float x0, x1, x2, x3;
                unpk2(A[rd][k * 2],     x0, x1);
                unpk2(A[rd][k * 2 + 1], x2, x3);
                int s = slotOf[t + 1][r];
                hgt[j + 0][s] = fmaxf(x0 + b0, 0.f);
                hgt[j + 1][s] = fmaxf(x1 + b1, 0.f);
                hgt[j + 2][s] = fmaxf(x2 + b2, 0.f);
                hgt[j + 3][s] = fmaxf(x3 + b3, 0.f);
            }
        }
        __syncthreads();
    }

    // classifier: 4 rows per warp
    #pragma unroll
    for (int rr = 0; rr < 4; rr++) {
        int r = warp * 4 + rr;
        float logit = NEG;
        if (lane < 10) {
            float acc = bout[lane];
            #pragma unroll 4
            for (int d = 0; d < 128; d++) acc += hgt[d][r] * Wout[d * 10 + lane];
            logit = acc;
        }
        float mx = logit;
        #pragma unroll
        for (int off = 8; off; off >>= 1)
            mx = fmaxf(mx, __shfl_xor_sync(0xffffffffu, mx, off, 16));
        float p = (lane < 10) ? expf(logit - mx) : 0.f;
        float s = p;
        #pragma unroll
        for (int off = 8; off; off >>= 1)
            s += __shfl_xor_sync(0xffffffffu, s, off, 16);
        if (lane < 10) out[(rowbase + r) * 10 + lane] = logit - mx - logf(s);
    }
}

// ---------------- launcher ----------------
extern "C" void kernel_launch(void* const* d_in, const int* in_sizes, int n_in,
                              void* d_out, int out_size)
{
    const float* x       = (const float*)d_in[0];
    const float* conv1_w = (const float*)d_in[1];
    const float* conv1_b = (const float*)d_in[2];
    const float* bn1_g   = (const float*)d_in[3];
    const float* bn1_b   = (const float*)d_in[4];
    const float* bn1_m   = (const float*)d_in[5];
    const float* bn1_v   = (const float*)d_in[6];
    const float* conv2_w = (const float*)d_in[7];
    const float* conv2_b = (const float*)d_in[8];
    const float* bn2_g   = (const float*)d_in[9];
    const float* bn2_b   = (const float*)d_in[10];
    const float* bn2_m   = (const float*)d_in[11];
    const float* bn2_v   = (const float*)d_in[12];
    const float* conv3_w = (const float*)d_in[13];
    const float* conv3_b = (const float*)d_in[14];
    const float* bn3_g   = (const float*)d_in[15];
    const float* bn3_b   = (const float*)d_in[16];
    const float* bn3_m   = (const float*)d_in[17];
    const float* bn3_v   = (const float*)d_in[18];
    const float* Wxh     = (const float*)d_in[19];
    const float* Whh     = (const float*)d_in[20];
    const float* bh      = (const float*)d_in[21];
    const float* Who     = (const float*)d_in[22];
    const float* bo      = (const float*)d_in[23];
    const float* emb     = (const float*)d_in[24];
    const float* Wexp    = (const float*)d_in[25];
    const float* bexp    = (const float*)d_in[26];
    const float* Wout    = (const float*)d_in[27];
    const float* bout    = (const float*)d_in[28];
    float* out = (float*)d_out;

    cudaFuncSetAttribute(k_conv_all, cudaFuncAttributeMaxDynamicSharedMemorySize, 81920);
    cudaFuncSetAttribute(k_expert, cudaFuncAttributeMaxDynamicSharedMemorySize, 196608);

    k_conv_all<<<BATCH, 288, 81920>>>(x,
        conv1_w, conv1_b, bn1_g, bn1_b, bn1_m, bn1_v,
        conv2_w, conv2_b, bn2_g, bn2_b, bn2_m, bn2_v,
        conv3_w, conv3_b, bn3_g, bn3_b, bn3_m, bn3_v);
    k_beam<<<BATCH, 256>>>(Whh, bh, Who, bo, emb, Wxh);
    k_expert<<<BATCH * 8 / EROWS, 256, 196608>>>(Wexp, bexp, Wout, bout, out);
}

// round 5
// speedup vs baseline: 1.0385x; 1.0154x over previous
#include <cuda_runtime.h>
#include <math.h>

#define BATCH 512
#define NEG   (-1e9f)

typedef unsigned long long u64;

__device__ __forceinline__ u64 pk2(float lo, float hi) {
    u64 r; asm("mov.b64 %0, {%1,%2};" : "=l"(r) : "f"(lo), "f"(hi)); return r;
}
__device__ __forceinline__ void fma2(u64& d, u64 a, u64 b) {
    asm("fma.rn.f32x2 %0, %1, %2, %3;" : "=l"(d) : "l"(a), "l"(b), "l"(d));
}
__device__ __forceinline__ void unpk2(u64 v, float& a, float& b) {
    asm("mov.b64 {%0,%1}, %2;" : "=f"(a), "=f"(b) : "l"(v));
}

// ---------------- scratch ----------------
__device__ float g_feat[BATCH * 128];
__device__ int   g_ops[BATCH * 8 * 3];

// =====================================================================
// Fused conv1+conv2+conv3 (+BN+ReLU+pool each) per image. (R2 version)
// =====================================================================
__global__ void __launch_bounds__(288, 2)
k_conv_all(const float* __restrict__ x,
           const float* __restrict__ w1, const float* __restrict__ cb1,
           const float* __restrict__ g1, const float* __restrict__ bb1,
           const float* __restrict__ m1, const float* __restrict__ v1,
           const float* __restrict__ w2, const float* __restrict__ cb2,
           const float* __restrict__ g2, const float* __restrict__ bb2,
           const float* __restrict__ m2, const float* __restrict__ v2,
           const float* __restrict__ w3, const float* __restrict__ cb3,
           const float* __restrict__ g3, const float* __restrict__ bb3,
           const float* __restrict__ m3, const float* __restrict__ v3)
{
    extern __shared__ float dsm[];
    float* sx  = dsm;               // 32 x 34
    float* sa1 = dsm + 1088;        // 32 x 15 x 18
    float* swb = sa1 + 8640;        // 9216 ([ic][oc][k])
    float* sa2 = swb + 9216;        // 32 x 6 x 8
    __shared__ float sw1[288];
    __shared__ float sc1s[32], sc1h[32], sc2s[32], sc2h[32], sc3s[32], sc3h[32];

    int b = blockIdx.x, tid = threadIdx.x;

    const float* xin = x + b * 1024;
    for (int i = tid; i < 1024; i += 288) {
        int row = i >> 5, col = i & 31;
        sx[row * 34 + col] = xin[i];
    }
    if (tid < 288) sw1[tid] = w1[tid];
    for (int i = tid; i < 9216; i += 288) {
        int oc = i / 288, rem = i - oc * 288, ic = rem / 9, k = rem - ic * 9;
        swb[(ic * 32 + oc) * 9 + k] = w2[i];
    }
    if (tid < 32) {
        float inv = g1[tid] * rsqrtf(v1[tid] + 1e-5f);
        sc1s[tid] = inv; sc1h[tid] = bb1[tid] - m1[tid] * inv + cb1[tid] * inv;
        inv = g2[tid] * rsqrtf(v2[tid] + 1e-5f);
        sc2s[tid] = inv; sc2h[tid] = bb2[tid] - m2[tid] * inv + cb2[tid] * inv;
        inv = g3[tid] * rsqrtf(v3[tid] + 1e-5f);
        sc3s[tid] = inv; sc3h[tid] = bb3[tid] - m3[tid] * inv + cb3[tid] * inv;
    }
    __syncthreads();

    // ---- conv1 ----
    for (int i = tid; i < 7200; i += 288) {
        int c = i / 225, p = i - c * 225, py = p / 15, px = p - py * 15;
        const float* wc = sw1 + c * 9;
        const float* ip = sx + (2 * py) * 34 + 2 * px;
        float r[4][4];
        #pragma unroll
        for (int rr = 0; rr < 4; rr++) {
            float2 a = *(const float2*)(ip + rr * 34);
            float2 q = *(const float2*)(ip + rr * 34 + 2);
            r[rr][0] = a.x; r[rr][1] = a.y; r[rr][2] = q.x; r[rr][3] = q.y;
        }
        float s00 = 0.f, s01 = 0.f, s10 = 0.f, s11 = 0.f;
        #pragma unroll
        for (int ky = 0; ky < 3; ky++)
            #pragma unroll
            for (int kx = 0; kx < 3; kx++) {
                float wv = wc[ky * 3 + kx];
                s00 += r[ky][kx]     * wv;  s01 += r[ky][kx + 1]     * wv;
                s10 += r[ky + 1][kx] * wv;  s11 += r[ky + 1][kx + 1] * wv;
            }
        float sc = sc1s[c], sh = sc1h[c];
        sa1[(c * 15 + py) * 18 + px] = 0.25f *
            (fmaxf(s00 * sc + sh, 0.f) + fmaxf(s01 * sc + sh, 0.f) +
             fmaxf(s10 * sc + sh, 0.f) + fmaxf(s11 * sc + sh, 0.f));
    }
    __syncthreads();

    // ---- conv2: thread = 4 oc x 1 pooled pos (plain FMA) ----
    {
        int ocg = tid / 36;
        int p = tid - ocg * 36, py = p / 6, px = p - py * 6;
        float s[4][4];
        #pragma unroll
        for (int a = 0; a < 4; a++)
            #pragma unroll
            for (int q = 0; q < 4; q++) s[a][q] = 0.f;
        for (int ic = 0; ic < 32; ic++) {
            const float* ip = sa1 + (ic * 15 + 2 * py) * 18 + 2 * px;
            float r[4][4];
            #pragma unroll
            for (int rr = 0; rr < 4; rr++) {
                float2 a = *(const float2*)(ip + rr * 18);
                float2 q = *(const float2*)(ip + rr * 18 + 2);
                r[rr][0] = a.x; r[rr][1] = a.y; r[rr][2] = q.x; r[rr][3] = q.y;
            }
            const float* wb = swb + (ic * 32 + ocg * 4) * 9;
            #pragma unroll
            for (int o4 = 0; o4 < 4; o4++) {
                const float* wp = wb + o4 * 9;
                #pragma unroll
                for (int ky = 0; ky < 3; ky++)
                    #pragma unroll
                    for (int kx = 0; kx < 3; kx++) {
                        float wv = wp[ky * 3 + kx];
                        s[o4][0] += r[ky][kx]     * wv;  s[o4][1] += r[ky][kx + 1]     * wv;
                        s[o4][2] += r[ky + 1][kx] * wv;  s[o4][3] += r[ky + 1][kx + 1] * wv;
                    }
            }
        }
        #pragma unroll
        for (int o4 = 0; o4 < 4; o4++) {
            int oc = ocg * 4 + o4;
            float sc = sc2s[oc], sh = sc2h[oc];
            sa2[(oc * 6 + py) * 8 + px] = 0.25f *
                (fmaxf(s[o4][0] * sc + sh, 0.f) + fmaxf(s[o4][1] * sc + sh, 0.f) +
                 fmaxf(s[o4][2] * sc + sh, 0.f) + fmaxf(s[o4][3] * sc + sh, 0.f));
        }
    }
    __syncthreads();

    for (int i = tid; i < 9216; i += 288) {
        int oc = i / 288, rem = i - oc * 288, ic = rem / 9, k = rem - ic * 9;
        swb[(ic * 32 + oc) * 9 + k] = w3[i];
    }
    __syncthreads();

    // ---- conv3 -> feat ----
    if (tid < 128) {
        int c = tid >> 2, q = tid & 3, y = q >> 1, xx = q & 1;
        float s00 = 0.f, s01 = 0.f, s10 = 0.f, s11 = 0.f;
        for (int ic = 0; ic < 32; ic++) {
            const float* ip = sa2 + (ic * 6 + 2 * y) * 8 + 2 * xx;
            float r[4][4];
            #pragma unroll
            for (int rr = 0; rr < 4; rr++) {
                float2 a = *(const float2*)(ip + rr * 8);
                float2 qq = *(const float2*)(ip + rr * 8 + 2);
                r[rr][0] = a.x; r[rr][1] = a.y; r[rr][2] = qq.x; r[rr][3] = qq.y;
            }
            const float* wp = swb + (ic * 32 + c) * 9;
            #pragma unroll
            for (int ky = 0; ky < 3; ky++)
                #pragma unroll
                for (int kx = 0; kx < 3; kx++) {
                    float wv = wp[ky * 3 + kx];
                    s00 += r[ky][kx]     * wv;  s01 += r[ky][kx + 1]     * wv;
                    s10 += r[ky + 1][kx] * wv;  s11 += r[ky + 1][kx + 1] * wv;
                }
        }
        float sc = sc3s[c], sh = sc3h[c];
        g_feat[b * 128 + tid] = 0.25f *
            (fmaxf(s00 * sc + sh, 0.f) + fmaxf(s01 * sc + sh, 0.f) +
             fmaxf(s10 * sc + sh, 0.f) + fmaxf(s11 * sc + sh, 0.f));
    }
}

// =====================================================================
// Beam search, restructured: GEMV of ALL 8 beams computed alongside
// logits (before top-k); top-k = single-warp shuffle section.
// 1 block / sample, 8 warps = 4 beam-pairs x 2 d-halves.
// =====================================================================
__global__ void __launch_bounds__(256)
k_beam(const float* __restrict__ Whh, const float* __restrict__ bh,
       const float* __restrict__ Who, const float* __restrict__ bo,
       const float* __restrict__ emb, const float* __restrict__ Wxh)
{
    __shared__ float shr[1024];                  // current hr (8 x 128)
    __shared__ float partA[8][128], partB[8][128];
    __shared__ float sexh[384], sWho[384], sbh[128], sbo[3];
    __shared__ float slog[24];
    __shared__ float sscore[8], nscore[8];
    __shared__ int   nbeam[8], nop[8], sops[2][3][8];

    int b = blockIdx.x, tid = threadIdx.x;
    int warp = tid >> 5, lane = tid & 31;

    for (int i = tid; i < 384; i += 256) sWho[i] = Who[i];
    if (tid < 128) sbh[tid] = bh[tid];
    if (tid < 3)   sbo[tid] = bo[tid];
    if (tid < 8)   sscore[tid] = (tid == 0) ? 0.f : NEG;
    for (int i = tid; i < 1024; i += 256) shr[i] = g_feat[b * 128 + (i & 127)];
    // exh = emb @ Wxh (3 x 128)
    for (int i = tid; i < 384; i += 256) {
        int o = i >> 7, j = i & 127;
        float acc = 0.f;
        #pragma unroll 4
        for (int d = 0; d < 128; d++) acc += emb[o * 128 + d] * Wxh[d * 128 + j];
        sexh[i] = acc;
    }
    __syncthreads();

    int cur = 0;
    for (int t = 0; t < 3; t++) {
        // ---- phase 1 (all warps): logits for beam=warp AND speculative
        //      GEMV of all 8 old beams through Whh ----
        {
            const float* h = shr + warp * 128;
            float a0 = 0.f, a1 = 0.f, a2 = 0.f;
            for (int d = lane; d < 128; d += 32) {
                float hv = h[d];
                a0 += hv * sWho[d * 3 + 0];
                a1 += hv * sWho[d * 3 + 1];
                a2 += hv * sWho[d * 3 + 2];
            }
            #pragma unroll
            for (int off = 16; off; off >>= 1) {
                a0 += __shfl_xor_sync(0xffffffffu, a0, off);
                a1 += __shfl_xor_sync(0xffffffffu, a1, off);
                a2 += __shfl_xor_sync(0xffffffffu, a2, off);
            }
            if (lane == 0) {
                slog[warp * 3 + 0] = a0 + sbo[0];
                slog[warp * 3 + 1] = a1 + sbo[1];
                slog[warp * 3 + 2] = a2 + sbo[2];
            }
        }
        {
            int pair = warp & 3, half = warp >> 2;
            int r0 = 2 * pair, r1 = r0 + 1;
            const float* h0 = shr + r0 * 128 + half * 64;
            const float* h1 = shr + r1 * 128 + half * 64;
            const float* Wb = Whh + half * 64 * 128 + 4 * lane;
            float4 a0 = make_float4(0.f, 0.f, 0.f, 0.f);
            float4 a1 = make_float4(0.f, 0.f, 0.f, 0.f);
            #pragma unroll 8
            for (int d = 0; d < 64; d++) {
                float4 w4 = *(const float4*)(Wb + d * 128);
                float v0 = h0[d], v1 = h1[d];
                a0.x += v0 * w4.x; a0.y += v0 * w4.y; a0.z += v0 * w4.z; a0.w += v0 * w4.w;
                a1.x += v1 * w4.x; a1.y += v1 * w4.y; a1.z += v1 * w4.z; a1.w += v1 * w4.w;
            }
            int j = 4 * lane;
            float (*dst)[128] = half ? partB : partA;
            dst[r0][j + 0] = a0.x; dst[r0][j + 1] = a0.y;
            dst[r0][j + 2] = a0.z; dst[r0][j + 3] = a0.w;
            dst[r1][j + 0] = a1.x; dst[r1][j + 1] = a1.y;
            dst[r1][j + 2] = a1.z; dst[r1][j + 3] = a1.w;
        }
        __syncthreads();

        // ---- phase 2 (warp 0 only): softmax + stable top-8 + history ----
        if (warp == 0) {
            float total = NEG * 4.f;   // lanes >= 24 never in top-8
            if (lane < 24) {
                int k = lane / 3;
                float y0 = slog[k * 3 + 0] * 2.5f;
                float y1 = slog[k * 3 + 1] * 2.5f;
                float y2 = slog[k * 3 + 2] * 2.5f;
                float own = slog[lane] * 2.5f;
                float mx = fmaxf(y0, fmaxf(y1, y2));
                float lse = logf(expf(y0 - mx) + expf(y1 - mx) + expf(y2 - mx));
                total = sscore[k] + (own - mx - lse);
            }
            int rank = 0;
            #pragma unroll
            for (int j = 0; j < 24; j++) {
                float u = __shfl_sync(0xffffffffu, total, j);
                rank += (u > total) || (u == total && j < lane);
            }
            if (lane < 24 && rank < 8) {
                nscore[rank] = total;
                nbeam[rank] = lane / 3;
                nop[rank]   = lane % 3;
            }
            __syncwarp();
            if (lane < 8) {
                sscore[lane] = nscore[lane];
                for (int s = 0; s < t; s++)
                    sops[1 - cur][s][lane] = sops[cur][s][nbeam[lane]];
                sops[1 - cur][t][lane] = nop[lane];
            }
        }
        __syncthreads();
        cur ^= 1;

        // ---- phase 3 (all threads): hr = tanh(gemv[sel] + exh[op] + bh) ----
        for (int i = tid; i < 1024; i += 256) {
            int k = i >> 7, d = i & 127;
            int src = nbeam[k];
            shr[i] = tanhf(partA[src][d] + partB[src][d] +
                           sexh[nop[k] * 128 + d] + sbh[d]);
        }
        __syncthreads();
    }
    if (tid < 8) {
        #pragma unroll
        for (int s = 0; s < 3; s++) g_ops[(b * 8 + tid) * 3 + s] = sops[cur][s][tid];
    }
}

// =====================================================================
// Expert chain: smem-resident weights (all 3), rows grouped by op.
// 128 blocks x 32 rows, 256 threads, 192KB dyn smem.
// =====================================================================
#define EROWS 32
__global__ void __launch_bounds__(256)
k_expert(const float* __restrict__ Wexp, const float* __restrict__ bexp,
         const float* __restrict__ Wout, const float* __restrict__ bout,
         float* __restrict__ out)
{
    extern __shared__ float sw[];          // 49152 floats = 192 KB
    __shared__ float hgt[128][40];         // transposed, group-ordered h
    __shared__ float sbias[384];
    __shared__ int sop[EROWS * 3];
    __shared__ int gperm[3][40];
    __shared__ int gop[3][10];
    __shared__ int slotOf[4][EROWS];
    __shared__ int sng[3];

    int tid = threadIdx.x, warp = tid >> 5, lane = tid & 31;
    int rowbase = blockIdx.x * EROWS;

    for (int i = tid; i < 49152; i += 256) sw[i] = Wexp[i];
    for (int i = tid; i < 384; i += 256) sbias[i] = bexp[i];
    if (tid < EROWS * 3) sop[tid] = g_ops[rowbase * 3 + tid];
    for (int i = tid; i < 128 * 40; i += 256) (&hgt[0][0])[i] = 0.f;
    __syncthreads();

    if (tid == 0) {
        for (int t = 0; t < 3; t++) {
            int cnt[3] = {0, 0, 0};
            int lists[3][EROWS];
            for (int j = 0; j < EROWS; j++) {
                int o = sop[j * 3 + t];
                lists[o][cnt[o]++] = j;
            }
            int g = 0;
            for (int o = 0; o < 3; o++)
                for (int base = 0; base < cnt[o]; base += 4) {
                    gop[t][g] = o;
                    for (int k = 0; k < 4; k++) {
                        int idx = base + k;
                        int r = (idx < cnt[o]) ? lists[o][idx] : -1;
                        gperm[t][g * 4 + k] = r;
                        if (r >= 0) slotOf[t][r] = g * 4 + k;
                    }
                    g++;
                }
            sng[t] = g;
        }
        for (int j = 0; j < EROWS; j++) slotOf[3][j] = j;
    }
    __syncthreads();

    // feat -> layer-0 slots
    for (int i = tid; i < EROWS * 128; i += 256) {
        int lr = i >> 7, d = i & 127;
        hgt[d][slotOf[0][lr]] = g_feat[((rowbase + lr) >> 3) * 128 + d];
    }
    __syncthreads();

    for (int t = 0; t < 3; t++) {
        int ng = sng[t];
        u64 A[2][8];
        #pragma unroll
        for (int rd = 0; rd < 2; rd++)
            #pragma unroll
            for (int z = 0; z < 8; z++) A[rd][z] = 0ull;

        #pragma unroll
        for (int rd = 0; rd < 2; rd++) {
            int g = warp + rd * 8;
            if (g >= ng) continue;
            const float* W = sw + gop[t][g] * 16384 + 4 * lane;
            #pragma unroll 4
            for (int d = 0; d < 128; d++) {
                float4 w4 = *(const float4*)(W + d * 128);
                float4 hv = *(const float4*)(&hgt[d][4 * g]);
                u64 wa = pk2(w4.x, w4.y), wb = pk2(w4.z, w4.w);
                u64 hx = pk2(hv.x, hv.x), hy = pk2(hv.y, hv.y);
                u64 hz = pk2(hv.z, hv.z), hw = pk2(hv.w, hv.w);
                fma2(A[rd][0], wa, hx); fma2(A[rd][1], wb, hx);
                fma2(A[rd][2], wa, hy); fma2(A[rd][3], wb, hy);
                fma2(A[rd][4], wa, hz); fma2(A[rd][5], wb, hz);
                fma2(A[rd][6], wa, hw); fma2(A[rd][7], wb, hw);
            }
        }
        __syncthreads();
        #pragma unroll
        for (int rd = 0; rd < 2; rd++) {
            int g = warp + rd * 8;
            if (g >= ng) continue;
            int o = gop[t][g];
            int j = 4 * lane;
            float b0 = sbias[o * 128 + j], b1 = sbias[o * 128 + j + 1];
            float b2 = sbias[o * 128 + j + 2], b3 = sbias[o * 128 + j + 3];
            #pragma unroll
            for (int k = 0; k < 4; k++) {
                int r = gperm[t][g * 4 + k];
                if (r < 0) continue;
                float x0, x1, x2, x3;
                unpk2(A[rd][k * 2],     x0, x1);
                unpk2(A[rd][k * 2 + 1], x2, x3);
                int s = slotOf[t + 1][r];
                hgt[j + 0][s] = fmaxf(x0 + b0, 0.f);
                hgt[j + 1][s] = fmaxf(x1 + b1, 0.f);
                hgt[j + 2][s] = fmaxf(x2 + b2, 0.f);
                hgt[j + 3][s] = fmaxf(x3 + b3, 0.f);
            }
        }
        __syncthreads();
    }

    // classifier: 4 rows per warp
    #pragma unroll
    for (int rr = 0; rr < 4; rr++) {
        int r = warp * 4 + rr;
        float logit = NEG;
        if (lane < 10) {
            float acc = bout[lane];
            #pragma unroll 4
            for (int d = 0; d < 128; d++) acc += hgt[d][r] * Wout[d * 10 + lane];
            logit = acc;
        }
        float mx = logit;
        #pragma unroll
        for (int off = 8; off; off >>= 1)
            mx = fmaxf(mx, __shfl_xor_sync(0xffffffffu, mx, off, 16));
        float p = (lane < 10) ? expf(logit - mx) : 0.f;
        float s = p;
        #pragma unroll
        for (int off = 8; off; off >>= 1)
            s += __shfl_xor_sync(0xffffffffu, s, off, 16);
        if (lane < 10) out[(rowbase + r) * 10 + lane] = logit - mx - logf(s);
    }
}

// ---------------- launcher ----------------
extern "C" void kernel_launch(void* const* d_in, const int* in_sizes, int n_in,
                              void* d_out, int out_size)
{
    const float* x       = (const float*)d_in[0];
    const float* conv1_w = (const float*)d_in[1];
    const float* conv1_b = (const float*)d_in[2];
    const float* bn1_g   = (const float*)d_in[3];
    const float* bn1_b   = (const float*)d_in[4];
    const float* bn1_m   = (const float*)d_in[5];
    const float* bn1_v   = (const float*)d_in[6];
    const float* conv2_w = (const float*)d_in[7];
    const float* conv2_b = (const float*)d_in[8];
    const float* bn2_g   = (const float*)d_in[9];
    const float* bn2_b   = (const float*)d_in[10];
    const float* bn2_m   = (const float*)d_in[11];
    const float* bn2_v   = (const float*)d_in[12];
    const float* conv3_w = (const float*)d_in[13];
    const float* conv3_b = (const float*)d_in[14];
    const float* bn3_g   = (const float*)d_in[15];
    const float* bn3_b   = (const float*)d_in[16];
    const float* bn3_m   = (const float*)d_in[17];
    const float* bn3_v   = (const float*)d_in[18];
    const float* Wxh     = (const float*)d_in[19];
    const float* Whh     = (const float*)d_in[20];
    const float* bh      = (const float*)d_in[21];
    const float* Who     = (const float*)d_in[22];
    const float* bo      = (const float*)d_in[23];
    const float* emb     = (const float*)d_in[24];
    const float* Wexp    = (const float*)d_in[25];
    const float* bexp    = (const float*)d_in[26];
    const float* Wout    = (const float*)d_in[27];
    const float* bout    = (const float*)d_in[28];
    float* out = (float*)d_out;

    cudaFuncSetAttribute(k_conv_all, cudaFuncAttributeMaxDynamicSharedMemorySize, 81920);
    cudaFuncSetAttribute(k_expert, cudaFuncAttributeMaxDynamicSharedMemorySize, 196608);

    k_conv_all<<<BATCH, 288, 81920>>>(x,
        conv1_w, conv1_b, bn1_g, bn1_b, bn1_m, bn1_v,
        conv2_w, conv2_b, bn2_g, bn2_b, bn2_m, bn2_v,
        conv3_w, conv3_b, bn3_g, bn3_b, bn3_m, bn3_v);
    k_beam<<<BATCH, 256>>>(Whh, bh, Who, bo, emb, Wxh);
    k_expert<<<BATCH * 8 / EROWS, 256, 196608>>>(Wexp, bexp, Wout, bout, out);
}